// round 15
// baseline (speedup 1.0000x reference)
#include <cuda_runtime.h>
#include <cuda_bf16.h>
#include <math.h>
#include <stdint.h>

// ---------------- problem constants ----------------
#define TT     1024      // tokens
#define HH     2048      // hidden
#define EE     32        // routed experts
#define TOPK   6
#define NGROUP 8
#define TOPKG  3
#define EPG    (EE/NGROUP)   // 4 experts per group
#define IMOE   768
#define ISH    1536          // 2 * IMOE
#define CAPE   768           // per-expert capacity
#define RSCALE 16.0f

// ---------------- scratch (static device globals; no allocation) ----------------
__device__ float g_logits[(size_t)TT*EE];            // router logits [1024,32]
__device__ float g_gu   [(size_t)TT*TOPK * 2*IMOE];  // routed gate_up outputs  [6144,1536]
__device__ float g_h    [(size_t)TT*TOPK * IMOE];    // routed silu*up          [6144, 768]
__device__ float g_y    [(size_t)TT*TOPK * HH];      // routed expert outputs   [6144,2048]
__device__ float g_gu_sh[(size_t)TT * 2*ISH];        // shared gate_up          [1024,3072]
__device__ float g_h_sh [(size_t)TT * ISH];          // shared silu*up          [1024,1536]
__device__ float g_wcomb[TT*TOPK];                   // combine weights (0 if dropped)
__device__ int   g_slot_tok [EE*CAPE];               // token index per expert slot
__device__ int   g_slot_flat[EE*CAPE];               // flat (t*K+k) per expert slot
__device__ int   g_cnt[EE];                          // per-expert assignment count

// ---------------- init ----------------
__global__ void init_kernel() {
    if (threadIdx.x < EE) g_cnt[threadIdx.x] = 0;
}

// ---------------- router logits: one thread per (t,e), SEQUENTIAL ascending-k fp32 fma ----
// Bit-replicates the reference's per-output single-accumulator ascending-k chain.
// DO NOT TOUCH: this exact ordering is what makes routing decisions match.
__global__ void logits_kernel(const float* __restrict__ x,
                              const float* __restrict__ gate_w) {
    __shared__ float sx[4][HH];               // 4 tokens staged, 32KB
    const int t0 = blockIdx.x * 4;
    const int tid = threadIdx.x;              // 128 threads: 4 tokens x 32 experts
    for (int i = tid; i < 4*HH; i += 128)
        sx[i >> 11][i & (HH-1)] = x[(size_t)(t0 + (i >> 11)) * HH + (i & (HH-1))];
    __syncthreads();

    const int tl = tid & 3;
    const int e  = tid >> 2;
    const float* gw = gate_w + (size_t)e * HH;
    float acc = 0.f;
    #pragma unroll 8
    for (int k = 0; k < HH; ++k)
        acc = fmaf(sx[tl][k], gw[k], acc);    // single chain, ascending k
    g_logits[(size_t)(t0 + tl) * EE + e] = acc;
}

// ---------------- selection: fp32 softmax (jax form) + group-limited top-k + dispatch ----
__global__ void select_kernel() {
    const int t = blockIdx.x * blockDim.x + threadIdx.x;
    if (t >= TT) return;
    const float* l = g_logits + (size_t)t * EE;

    float mx = l[0];
    for (int e = 1; e < EE; ++e) mx = fmaxf(mx, l[e]);
    float ex[EE]; float sum = 0.f;
    for (int e = 0; e < EE; ++e) { ex[e] = expf(l[e] - mx); sum += ex[e]; }
    float sc[EE];
    for (int e = 0; e < EE; ++e) sc[e] = ex[e] / sum;

    float gs[NGROUP];
    for (int g = 0; g < NGROUP; ++g) {
        float m = sc[g * EPG];
        for (int j = 1; j < EPG; ++j) m = fmaxf(m, sc[g * EPG + j]);
        gs[g] = m;
    }
    bool gsel[NGROUP];
    for (int g = 0; g < NGROUP; ++g) gsel[g] = false;
    for (int r = 0; r < TOPKG; ++r) {
        int best = -1; float bv = -1e30f;
        for (int g = 0; g < NGROUP; ++g)
            if (!gsel[g] && gs[g] > bv) { bv = gs[g]; best = g; }
        gsel[best] = true;
    }
    float ms[EE];
    for (int e = 0; e < EE; ++e) ms[e] = gsel[e / EPG] ? sc[e] : 0.f;
    for (int k = 0; k < TOPK; ++k) {
        int best = 0; float bv = -1.f;
        for (int e = 0; e < EE; ++e)
            if (ms[e] > bv) { bv = ms[e]; best = e; }
        ms[best] = -1.f;
        const int flat = t * TOPK + k;
        const int pos = atomicAdd(&g_cnt[best], 1);
        if (pos < CAPE) {
            g_slot_tok [best * CAPE + pos] = t;
            g_slot_flat[best * CAPE + pos] = flat;
            g_wcomb[flat] = bv;
        } else {
            g_wcomb[flat] = 0.f;
        }
    }
}

// ================= TF32 tensor-core NT GEMM (R8 body, templated on BM) =================
// cp.async double-buffered, prefetch at loop top, wait_group 1; cvt.rna.tf32 at
// fragment load (cublas numerics), fp32 acc. BMTx128x32 tile, 256 thr, m16n8k8.
// Per-output accumulation chain is independent of BMT -> bitwise-identical results.
#define BN 128
#define BKK 32
#define SPAD 4
#define SROW (BKK + SPAD)           // 36 words; 144B row stride (16B-aligned)
#define STG_B (BN * SROW)           // B stage floats (4608)
#define SMEM_MAX ((2*128*SROW + 2*STG_B) * 4)   // worst case (BMT=128): 73728B

__device__ __forceinline__ uint32_t tf32b(float x) {
    uint32_t u;
    asm("cvt.rna.tf32.f32 %0, %1;" : "=r"(u) : "f"(x));
    return u;
}

__device__ __forceinline__ void mma_tf32(float c[4], const uint32_t a[4], const uint32_t b[2]) {
    asm volatile(
        "mma.sync.aligned.m16n8k8.row.col.f32.tf32.tf32.f32 "
        "{%0,%1,%2,%3}, {%4,%5,%6,%7}, {%8,%9}, {%0,%1,%2,%3};\n"
        : "+f"(c[0]), "+f"(c[1]), "+f"(c[2]), "+f"(c[3])
        : "r"(a[0]), "r"(a[1]), "r"(a[2]), "r"(a[3]), "r"(b[0]), "r"(b[1]));
}

__device__ __forceinline__ void cp16(uint32_t smem_addr, const float* gptr, int srcsize) {
    asm volatile("cp.async.cg.shared.global [%0], [%1], 16, %2;\n"
                 :: "r"(smem_addr), "l"(gptr), "r"(srcsize));
}

// bx, by = tile coordinates (grid-fused callers decode them)
template<int BMT>
__device__ __forceinline__ void gemm_tc_body(
    int bx, int by,
    const float* __restrict__ A, int lda,
    const float* __restrict__ B,            // row-major [N, Klen]
    float* __restrict__ C, int ldc,
    const int* __restrict__ arow,           // nullable: A row = arow[m]
    const int* __restrict__ crow,           // nullable: C row = crow[m]
    int M, int Klen)
{
    constexpr int AP = BMT / 32;            // A cp.async passes (rows/32)
    constexpr int MT = BMT / 32;            // m-subtiles per warp (16 rows each)
    constexpr int STG_A = BMT * SROW;       // A stage floats

    const int m0 = by * BMT;
    if (m0 >= M) return;
    const int n0 = bx * BN;

    extern __shared__ float smem[];
    float* Asf = smem;                        // [2][BMT][SROW]
    float* Bsf = smem + 2 * STG_A;            // [2][BN][SROW]
    const uint32_t smem_base = (uint32_t)__cvta_generic_to_shared(smem);
    const uint32_t As_u = smem_base;
    const uint32_t Bs_u = smem_base + 2 * STG_A * 4;

    const int tid  = threadIdx.x;
    const int warp = tid >> 5, lane = tid & 31;
    const int wm = (warp & 1) * (BMT / 2);    // warp m-offset within block
    const int wn = (warp >> 1) * 32;          // warp n-offset within block
    const int gid = lane >> 2, tig = lane & 3;

    // global-load mapping: each thread cp.async's one float4 per pass
    const int lrow = tid >> 3;                // 0..31
    const int lcol = (tid & 7) * 4;           // 0,4,...,28

    // resolve gathered A rows once
    long long arows[AP]; int asz[AP];
    #pragma unroll
    for (int p = 0; p < AP; ++p) {
        const int m = m0 + lrow + p * 32;
        const bool ok = m < M;
        asz[p] = ok ? 16 : 0;                 // cp.async src-size 0 => zero-fill
        arows[p] = ok ? (arow ? arow[m] : m) : 0;
    }
    const long long brow = (long long)(n0 + lrow) * Klen;

    float acc[MT][4][4];
    #pragma unroll
    for (int i = 0; i < MT; ++i)
        #pragma unroll
        for (int j = 0; j < 4; ++j)
            #pragma unroll
            for (int r = 0; r < 4; ++r) acc[i][j][r] = 0.f;

    auto prefetch = [&](int st, int k0) {
        const uint32_t abase = As_u + (uint32_t)(st * STG_A) * 4;
        const uint32_t bbase = Bs_u + (uint32_t)(st * STG_B) * 4;
        #pragma unroll
        for (int p = 0; p < AP; ++p) {
            const int r = lrow + p * 32;
            cp16(abase + (uint32_t)(r * SROW + lcol) * 4,
                 A + arows[p] * (long long)lda + k0 + lcol, asz[p]);
        }
        #pragma unroll
        for (int p = 0; p < 4; ++p) {
            const int r = lrow + p * 32;
            cp16(bbase + (uint32_t)(r * SROW + lcol) * 4,
                 B + brow + (long long)p * 32 * Klen + k0 + lcol, 16);
        }
        asm volatile("cp.async.commit_group;\n");
    };

    prefetch(0, 0);

    int s = 0;
    for (int k0 = 0; k0 < Klen; k0 += BKK, s ^= 1) {
        const bool has_next = (k0 + BKK) < Klen;
        if (has_next) prefetch(s ^ 1, k0 + BKK);
        if (has_next) asm volatile("cp.async.wait_group 1;\n");
        else          asm volatile("cp.async.wait_group 0;\n");
        __syncthreads();

        const float* As = Asf + s * STG_A;
        const float* Bs = Bsf + s * STG_B;
        #pragma unroll
        for (int kk = 0; kk < BKK; kk += 8) {
            uint32_t af[MT][4], bf[4][2];
            #pragma unroll
            for (int mt = 0; mt < MT; ++mt) {
                const int r = wm + mt * 16 + gid;
                af[mt][0] = tf32b(As[ r      * SROW + kk + tig    ]);
                af[mt][1] = tf32b(As[(r + 8) * SROW + kk + tig    ]);
                af[mt][2] = tf32b(As[ r      * SROW + kk + tig + 4]);
                af[mt][3] = tf32b(As[(r + 8) * SROW + kk + tig + 4]);
            }
            #pragma unroll
            for (int nt = 0; nt < 4; ++nt) {
                const int r = wn + nt * 8 + gid;
                bf[nt][0] = tf32b(Bs[r * SROW + kk + tig    ]);
                bf[nt][1] = tf32b(Bs[r * SROW + kk + tig + 4]);
            }
            #pragma unroll
            for (int mt = 0; mt < MT; ++mt)
                #pragma unroll
                for (int nt = 0; nt < 4; ++nt)
                    mma_tf32(acc[mt][nt], af[mt], bf[nt]);
        }
        __syncthreads();
    }

    // epilogue: c0,c1 at (gid, 2*tig), c2,c3 at (gid+8, 2*tig)
    #pragma unroll
    for (int mt = 0; mt < MT; ++mt) {
        const int ma = m0 + wm + mt * 16 + gid;
        const int mb = ma + 8;
        #pragma unroll
        for (int nt = 0; nt < 4; ++nt) {
            const int col = n0 + wn + nt * 8 + 2 * tig;
            if (ma < M) {
                const long long r = crow ? crow[ma] : ma;
                *(float2*)(C + r * (long long)ldc + col) = make_float2(acc[mt][nt][0], acc[mt][nt][1]);
            }
            if (mb < M) {
                const long long r = crow ? crow[mb] : mb;
                *(float2*)(C + r * (long long)ldc + col) = make_float2(acc[mt][nt][2], acc[mt][nt][3]);
            }
        }
    }
}

// ---- fused GEMM stage 1: routed gate_up (BM=64) + shared gate_up (BM=128) ----
#define R1Y (CAPE/64)                         // 12 y-tiles per expert
#define R1_BLOCKS (12 * R1Y * EE)             // 4608
#define S1_BLOCKS (24 * 8)                    // 192
__global__ void __launch_bounds__(256, 2) gemm_stage1(const float* __restrict__ x,
                                                      const float* __restrict__ w13,
                                                      const float* __restrict__ sgu) {
    const int bid = blockIdx.x;
    if (bid < R1_BLOCKS) {
        const int e   = bid / (12 * R1Y);
        const int rem = bid % (12 * R1Y);
        const int by  = rem / 12, bx = rem % 12;
        const int M = min(g_cnt[e], CAPE);
        gemm_tc_body<64>(bx, by, x, HH,
                         w13 + (long long)e * (2*IMOE) * HH,
                         g_gu, 2*IMOE,
                         g_slot_tok + e*CAPE, g_slot_flat + e*CAPE,
                         M, HH);
    } else {
        const int sid = bid - R1_BLOCKS;
        const int by = sid / 24, bx = sid % 24;
        gemm_tc_body<128>(bx, by, x, HH, sgu, g_gu_sh, 2*ISH, nullptr, nullptr, TT, HH);
    }
}

// ---- fused GEMM stage 2: routed down (BM=64) + shared down (BM=128) ----
#define R2_BLOCKS (16 * R1Y * EE)             // 6144
#define S2_BLOCKS (16 * 8)                    // 128
__global__ void __launch_bounds__(256, 2) gemm_stage2(const float* __restrict__ w2,
                                                      const float* __restrict__ sdn,
                                                      float* __restrict__ out) {
    const int bid = blockIdx.x;
    if (bid < R2_BLOCKS) {
        const int e   = bid / (16 * R1Y);
        const int rem = bid % (16 * R1Y);
        const int by  = rem / 16, bx = rem % 16;
        const int M = min(g_cnt[e], CAPE);
        gemm_tc_body<64>(bx, by, g_h, IMOE,
                         w2 + (long long)e * HH * IMOE,
                         g_y, HH,
                         g_slot_flat + e*CAPE, g_slot_flat + e*CAPE,
                         M, IMOE);
    } else {
        const int sid = bid - R2_BLOCKS;
        const int by = sid / 16, bx = sid % 16;
        gemm_tc_body<128>(bx, by, g_h_sh, ISH, sdn, out, HH, nullptr, nullptr, TT, ISH);
    }
}

// ---------------- fused SwiGLU elementwise (exact fp32) ----------------
__global__ void swiglu_fused() {
    const int bid = blockIdx.x;
    if (bid < EE * CAPE) {
        const int e = bid / CAPE, pos = bid % CAPE;
        if (pos >= g_cnt[e]) return;
        const int flat = g_slot_flat[bid];
        const float* gu = g_gu + (long long)flat * (2*IMOE);
        float* h = g_h + (long long)flat * IMOE;
        for (int i = threadIdx.x; i < IMOE; i += blockDim.x) {
            float g = gu[i], u = gu[i + IMOE];
            h[i] = u * g / (1.f + expf(-g));
        }
    } else {
        const int t = bid - EE * CAPE;
        const float* gu = g_gu_sh + (long long)t * (2*ISH);
        float* h = g_h_sh + (long long)t * ISH;
        for (int i = threadIdx.x; i < ISH; i += blockDim.x) {
            float g = gu[i], u = gu[i + ISH];
            h[i] = u * g / (1.f + expf(-g));
        }
    }
}

// ---------------- combine: out += SCALE * sum_k w_k * y_k ----------------
__global__ void combine_kernel(float* __restrict__ out) {
    const int t = blockIdx.x;
    const int base = t * TOPK;
    float w[TOPK];
    #pragma unroll
    for (int k = 0; k < TOPK; ++k) w[k] = g_wcomb[base + k];
    float* orow = out + (long long)t * HH;
    for (int h = threadIdx.x; h < HH; h += blockDim.x) {
        float r = 0.f;
        #pragma unroll
        for (int k = 0; k < TOPK; ++k)
            r += w[k] * g_y[(long long)(base + k) * HH + h];
        orow[h] += RSCALE * r;
    }
}

// ---------------- launch ----------------
extern "C" void kernel_launch(void* const* d_in, const int* in_sizes, int n_in,
                              void* d_out, int out_size) {
    const float* x     = (const float*)d_in[0];   // [T,H]
    const float* gatew = (const float*)d_in[1];   // [E,H]
    const float* w13   = (const float*)d_in[2];   // [E,2I,H]
    const float* w2    = (const float*)d_in[3];   // [E,H,I]
    const float* sgu   = (const float*)d_in[4];   // [2*ISH,H]
    const float* sdn   = (const float*)d_in[5];   // [H,ISH]
    float* out = (float*)d_out;                   // [T,H]

    static bool attr_set = false;
    if (!attr_set) {
        cudaFuncSetAttribute(gemm_stage1, cudaFuncAttributeMaxDynamicSharedMemorySize, SMEM_MAX);
        cudaFuncSetAttribute(gemm_stage2, cudaFuncAttributeMaxDynamicSharedMemorySize, SMEM_MAX);
        attr_set = true;
    }

    init_kernel<<<1, 32>>>();
    logits_kernel<<<TT/4, 128>>>(x, gatew);
    select_kernel<<<4, 256>>>();

    // stage 1: routed gate_up (BM=64, low padding) + shared gate_up fused
    gemm_stage1<<<R1_BLOCKS + S1_BLOCKS, 256, SMEM_MAX>>>(x, w13, sgu);

    // fused swiglu (routed slots + shared tokens)
    swiglu_fused<<<EE*CAPE + TT, 256>>>();

    // stage 2: routed down (BM=64) + shared down fused (shared2 writes out fully)
    gemm_stage2<<<R2_BLOCKS + S2_BLOCKS, 256, SMEM_MAX>>>(w2, sdn, out);

    // combine routed into out
    combine_kernel<<<TT, 256>>>(out);
}

// round 16
// speedup vs baseline: 1.0625x; 1.0625x over previous
#include <cuda_runtime.h>
#include <cuda_bf16.h>
#include <math.h>
#include <stdint.h>

// ---------------- problem constants ----------------
#define TT     1024      // tokens
#define HH     2048      // hidden
#define EE     32        // routed experts
#define TOPK   6
#define NGROUP 8
#define TOPKG  3
#define EPG    (EE/NGROUP)   // 4 experts per group
#define IMOE   768
#define ISH    1536          // 2 * IMOE
#define CAPE   768           // per-expert capacity
#define RSCALE 16.0f

// ---------------- scratch (static device globals; no allocation) ----------------
__device__ float g_logits[(size_t)TT*EE];            // router logits [1024,32]
__device__ float g_h    [(size_t)TT*TOPK * IMOE];    // routed silu*up          [6144, 768]
__device__ float g_y    [(size_t)TT*TOPK * HH];      // routed expert outputs   [6144,2048]
__device__ float g_h_sh [(size_t)TT * ISH];          // shared silu*up          [1024,1536]
__device__ float g_wcomb[TT*TOPK];                   // combine weights (0 if dropped)
__device__ int   g_slot_tok [EE*CAPE];               // token index per expert slot
__device__ int   g_slot_flat[EE*CAPE];               // flat (t*K+k) per expert slot
__device__ int   g_cnt[EE];                          // per-expert assignment count

// ---------------- init ----------------
__global__ void init_kernel() {
    if (threadIdx.x < EE) g_cnt[threadIdx.x] = 0;
}

// ---------------- router logits: one thread per (t,e), SEQUENTIAL ascending-k fp32 fma ----
// Bit-replicates the reference's per-output single-accumulator ascending-k chain.
// DO NOT TOUCH: this exact ordering is what makes routing decisions match.
__global__ void logits_kernel(const float* __restrict__ x,
                              const float* __restrict__ gate_w) {
    __shared__ float sx[4][HH];               // 4 tokens staged, 32KB
    const int t0 = blockIdx.x * 4;
    const int tid = threadIdx.x;              // 128 threads: 4 tokens x 32 experts
    for (int i = tid; i < 4*HH; i += 128)
        sx[i >> 11][i & (HH-1)] = x[(size_t)(t0 + (i >> 11)) * HH + (i & (HH-1))];
    __syncthreads();

    const int tl = tid & 3;
    const int e  = tid >> 2;
    const float* gw = gate_w + (size_t)e * HH;
    float acc = 0.f;
    #pragma unroll 8
    for (int k = 0; k < HH; ++k)
        acc = fmaf(sx[tl][k], gw[k], acc);    // single chain, ascending k
    g_logits[(size_t)(t0 + tl) * EE + e] = acc;
}

// ---------------- selection: fp32 softmax (jax form) + group-limited top-k + dispatch ----
__global__ void select_kernel() {
    const int t = blockIdx.x * blockDim.x + threadIdx.x;
    if (t >= TT) return;
    const float* l = g_logits + (size_t)t * EE;

    float mx = l[0];
    for (int e = 1; e < EE; ++e) mx = fmaxf(mx, l[e]);
    float ex[EE]; float sum = 0.f;
    for (int e = 0; e < EE; ++e) { ex[e] = expf(l[e] - mx); sum += ex[e]; }
    float sc[EE];
    for (int e = 0; e < EE; ++e) sc[e] = ex[e] / sum;

    float gs[NGROUP];
    for (int g = 0; g < NGROUP; ++g) {
        float m = sc[g * EPG];
        for (int j = 1; j < EPG; ++j) m = fmaxf(m, sc[g * EPG + j]);
        gs[g] = m;
    }
    bool gsel[NGROUP];
    for (int g = 0; g < NGROUP; ++g) gsel[g] = false;
    for (int r = 0; r < TOPKG; ++r) {
        int best = -1; float bv = -1e30f;
        for (int g = 0; g < NGROUP; ++g)
            if (!gsel[g] && gs[g] > bv) { bv = gs[g]; best = g; }
        gsel[best] = true;
    }
    float ms[EE];
    for (int e = 0; e < EE; ++e) ms[e] = gsel[e / EPG] ? sc[e] : 0.f;
    for (int k = 0; k < TOPK; ++k) {
        int best = 0; float bv = -1.f;
        for (int e = 0; e < EE; ++e)
            if (ms[e] > bv) { bv = ms[e]; best = e; }
        ms[best] = -1.f;
        const int flat = t * TOPK + k;
        const int pos = atomicAdd(&g_cnt[best], 1);
        if (pos < CAPE) {
            g_slot_tok [best * CAPE + pos] = t;
            g_slot_flat[best * CAPE + pos] = flat;
            g_wcomb[flat] = bv;
        } else {
            g_wcomb[flat] = 0.f;
        }
    }
}

// ---------------- shared GEMM machinery (R8 numerics) ----------------
#define BKK 32
#define SPAD 4
#define SROW (BKK + SPAD)           // 36 words; 144B row stride (16B-aligned)

__device__ __forceinline__ uint32_t tf32b(float x) {
    uint32_t u;
    asm("cvt.rna.tf32.f32 %0, %1;" : "=r"(u) : "f"(x));
    return u;
}

__device__ __forceinline__ void mma_tf32(float c[4], const uint32_t a[4], const uint32_t b[2]) {
    asm volatile(
        "mma.sync.aligned.m16n8k8.row.col.f32.tf32.tf32.f32 "
        "{%0,%1,%2,%3}, {%4,%5,%6,%7}, {%8,%9}, {%0,%1,%2,%3};\n"
        : "+f"(c[0]), "+f"(c[1]), "+f"(c[2]), "+f"(c[3])
        : "r"(a[0]), "r"(a[1]), "r"(a[2]), "r"(a[3]), "r"(b[0]), "r"(b[1]));
}

__device__ __forceinline__ void cp16(uint32_t smem_addr, const float* gptr, int srcsize) {
    asm volatile("cp.async.cg.shared.global [%0], [%1], 16, %2;\n"
                 :: "r"(smem_addr), "l"(gptr), "r"(srcsize));
}

// ================= STAGE 1: fused gate+up GEMM with SiLU epilogue =================
// Block computes a [128 rows x 64 inter-cols] slice of BOTH gate and up halves,
// then writes h = silu(g)*u directly. Same mma/slab count as the 128x128 body.
#define S1_STG_A  (128 * SROW)               // 4608 floats
#define S1_STG_B  (64 * SROW)                // 2304 floats
#define S1_SMEM   ((2*S1_STG_A + 4*S1_STG_B) * 4)   // 73728 B

__device__ __forceinline__ void gemm_swiglu_body(
    int bx, int by,
    const float* __restrict__ A, int lda,
    const float* __restrict__ B, int uoff,   // gate rows at B, up rows at B+(uoff+..)
    float* __restrict__ Hout, int ldh,
    const int* __restrict__ arow,            // nullable
    const int* __restrict__ crow,            // nullable
    int M, int Klen)
{
    const int m0 = by * 128;
    if (m0 >= M) return;
    const int n0h = bx * 64;                  // intermediate-col slice base

    extern __shared__ float smem[];
    float* Asf = smem;                        // [2][128][SROW]
    float* Bgf = smem + 2 * S1_STG_A;         // [2][64][SROW]
    float* Buf = Bgf + 2 * S1_STG_B;          // [2][64][SROW]
    const uint32_t sb = (uint32_t)__cvta_generic_to_shared(smem);
    const uint32_t As_u = sb;
    const uint32_t Bg_u = sb + 2 * S1_STG_A * 4;
    const uint32_t Bu_u = Bg_u + 2 * S1_STG_B * 4;

    const int tid  = threadIdx.x;
    const int warp = tid >> 5, lane = tid & 31;
    const int wm = (warp & 3) * 32;           // 4 warps along m
    const int wn = (warp >> 2) * 32;          // 2 warps along n (64 cols)
    const int gid = lane >> 2, tig = lane & 3;

    const int lrow = tid >> 3;                // 0..31
    const int lcol = (tid & 7) * 4;

    long long arows[4]; int asz[4];
    #pragma unroll
    for (int p = 0; p < 4; ++p) {
        const int m = m0 + lrow + p * 32;
        const bool ok = m < M;
        asz[p] = ok ? 16 : 0;
        arows[p] = ok ? (arow ? arow[m] : m) : 0;
    }
    const long long bgrow = (long long)(n0h + lrow) * Klen;
    const long long burow = (long long)(uoff + n0h + lrow) * Klen;

    float accG[2][4][4], accU[2][4][4];
    #pragma unroll
    for (int i = 0; i < 2; ++i)
        #pragma unroll
        for (int j = 0; j < 4; ++j)
            #pragma unroll
            for (int r = 0; r < 4; ++r) { accG[i][j][r] = 0.f; accU[i][j][r] = 0.f; }

    auto prefetch = [&](int st, int k0) {
        const uint32_t ab = As_u + (uint32_t)(st * S1_STG_A) * 4;
        const uint32_t gb = Bg_u + (uint32_t)(st * S1_STG_B) * 4;
        const uint32_t ub = Bu_u + (uint32_t)(st * S1_STG_B) * 4;
        #pragma unroll
        for (int p = 0; p < 4; ++p)
            cp16(ab + (uint32_t)((lrow + p * 32) * SROW + lcol) * 4,
                 A + arows[p] * (long long)lda + k0 + lcol, asz[p]);
        #pragma unroll
        for (int p = 0; p < 2; ++p) {
            cp16(gb + (uint32_t)((lrow + p * 32) * SROW + lcol) * 4,
                 B + bgrow + (long long)p * 32 * Klen + k0 + lcol, 16);
            cp16(ub + (uint32_t)((lrow + p * 32) * SROW + lcol) * 4,
                 B + burow + (long long)p * 32 * Klen + k0 + lcol, 16);
        }
        asm volatile("cp.async.commit_group;\n");
    };

    prefetch(0, 0);

    int s = 0;
    for (int k0 = 0; k0 < Klen; k0 += BKK, s ^= 1) {
        const bool has_next = (k0 + BKK) < Klen;
        if (has_next) prefetch(s ^ 1, k0 + BKK);
        if (has_next) asm volatile("cp.async.wait_group 1;\n");
        else          asm volatile("cp.async.wait_group 0;\n");
        __syncthreads();

        const float* As = Asf + s * S1_STG_A;
        const float* Bg = Bgf + s * S1_STG_B;
        const float* Bu = Buf + s * S1_STG_B;
        #pragma unroll
        for (int kk = 0; kk < BKK; kk += 8) {
            uint32_t af[2][4], bg[4][2], bu[4][2];
            #pragma unroll
            for (int mt = 0; mt < 2; ++mt) {
                const int r = wm + mt * 16 + gid;
                af[mt][0] = tf32b(As[ r      * SROW + kk + tig    ]);
                af[mt][1] = tf32b(As[(r + 8) * SROW + kk + tig    ]);
                af[mt][2] = tf32b(As[ r      * SROW + kk + tig + 4]);
                af[mt][3] = tf32b(As[(r + 8) * SROW + kk + tig + 4]);
            }
            #pragma unroll
            for (int nt = 0; nt < 4; ++nt) {
                const int r = wn + nt * 8 + gid;
                bg[nt][0] = tf32b(Bg[r * SROW + kk + tig    ]);
                bg[nt][1] = tf32b(Bg[r * SROW + kk + tig + 4]);
                bu[nt][0] = tf32b(Bu[r * SROW + kk + tig    ]);
                bu[nt][1] = tf32b(Bu[r * SROW + kk + tig + 4]);
            }
            #pragma unroll
            for (int mt = 0; mt < 2; ++mt)
                #pragma unroll
                for (int nt = 0; nt < 4; ++nt) {
                    mma_tf32(accG[mt][nt], af[mt], bg[nt]);
                    mma_tf32(accU[mt][nt], af[mt], bu[nt]);
                }
        }
        __syncthreads();
    }

    // fused SiLU epilogue: h = u * g / (1 + exp(-g)); same formula as before
    #pragma unroll
    for (int mt = 0; mt < 2; ++mt) {
        const int ma = m0 + wm + mt * 16 + gid;
        const int mb = ma + 8;
        #pragma unroll
        for (int nt = 0; nt < 4; ++nt) {
            const int col = n0h + wn + nt * 8 + 2 * tig;
            if (ma < M) {
                const float g0 = accG[mt][nt][0], u0 = accU[mt][nt][0];
                const float g1 = accG[mt][nt][1], u1 = accU[mt][nt][1];
                const long long r = crow ? crow[ma] : ma;
                *(float2*)(Hout + r * (long long)ldh + col) =
                    make_float2(u0 * g0 / (1.f + expf(-g0)), u1 * g1 / (1.f + expf(-g1)));
            }
            if (mb < M) {
                const float g2 = accG[mt][nt][2], u2 = accU[mt][nt][2];
                const float g3 = accG[mt][nt][3], u3 = accU[mt][nt][3];
                const long long r = crow ? crow[mb] : mb;
                *(float2*)(Hout + r * (long long)ldh + col) =
                    make_float2(u2 * g2 / (1.f + expf(-g2)), u3 * g3 / (1.f + expf(-g3)));
            }
        }
    }
}

// ---- stage 1 fused grid: routed (12 slices x 6 y x 32 e) + shared (24 slices x 8 y) ----
#define R1_BLOCKS (12 * 6 * EE)              // 2304
#define S1_BLOCKS (24 * 8)                   // 192
__global__ void __launch_bounds__(256, 2) gemm_stage1(const float* __restrict__ x,
                                                      const float* __restrict__ w13,
                                                      const float* __restrict__ sgu) {
    const int bid = blockIdx.x;
    if (bid < R1_BLOCKS) {
        const int e   = bid / 72;
        const int rem = bid % 72;
        const int by  = rem / 12, bx = rem % 12;
        const int M = min(g_cnt[e], CAPE);
        gemm_swiglu_body(bx, by, x, HH,
                         w13 + (long long)e * (2*IMOE) * HH, IMOE,
                         g_h, IMOE,
                         g_slot_tok + e*CAPE, g_slot_flat + e*CAPE,
                         M, HH);
    } else {
        const int sid = bid - R1_BLOCKS;
        const int by = sid / 24, bx = sid % 24;
        gemm_swiglu_body(bx, by, x, HH, sgu, ISH, g_h_sh, ISH,
                         nullptr, nullptr, TT, HH);
    }
}

// ================= STAGE 2: plain 128x128 GEMM (exact R8/R14 body) =================
#define BM 128
#define BN 128
#define STG_A (BM * SROW)
#define STG_B (BN * SROW)
#define S2_SMEM ((2*STG_A + 2*STG_B) * 4)    // 73728 B

__device__ __forceinline__ void gemm_tc_body(
    int bx, int by,
    const float* __restrict__ A, int lda,
    const float* __restrict__ B,
    float* __restrict__ C, int ldc,
    const int* __restrict__ arow,
    const int* __restrict__ crow,
    int M, int Klen)
{
    const int m0 = by * BM;
    if (m0 >= M) return;
    const int n0 = bx * BN;

    extern __shared__ float smem[];
    float* Asf = smem;
    float* Bsf = smem + 2 * STG_A;
    const uint32_t smem_base = (uint32_t)__cvta_generic_to_shared(smem);
    const uint32_t As_u = smem_base;
    const uint32_t Bs_u = smem_base + 2 * STG_A * 4;

    const int tid  = threadIdx.x;
    const int warp = tid >> 5, lane = tid & 31;
    const int wm = (warp & 1) * 64;
    const int wn = (warp >> 1) * 32;
    const int gid = lane >> 2, tig = lane & 3;

    const int lrow = tid >> 3;
    const int lcol = (tid & 7) * 4;

    long long arows[4]; int asz[4];
    #pragma unroll
    for (int p = 0; p < 4; ++p) {
        const int m = m0 + lrow + p * 32;
        const bool ok = m < M;
        asz[p] = ok ? 16 : 0;
        arows[p] = ok ? (arow ? arow[m] : m) : 0;
    }
    const long long brow = (long long)(n0 + lrow) * Klen;

    float acc[4][4][4];
    #pragma unroll
    for (int i = 0; i < 4; ++i)
        #pragma unroll
        for (int j = 0; j < 4; ++j)
            #pragma unroll
            for (int r = 0; r < 4; ++r) acc[i][j][r] = 0.f;

    auto prefetch = [&](int st, int k0) {
        const uint32_t abase = As_u + (uint32_t)(st * STG_A) * 4;
        const uint32_t bbase = Bs_u + (uint32_t)(st * STG_B) * 4;
        #pragma unroll
        for (int p = 0; p < 4; ++p) {
            const int r = lrow + p * 32;
            cp16(abase + (uint32_t)(r * SROW + lcol) * 4,
                 A + arows[p] * (long long)lda + k0 + lcol, asz[p]);
            cp16(bbase + (uint32_t)(r * SROW + lcol) * 4,
                 B + brow + (long long)p * 32 * Klen + k0 + lcol, 16);
        }
        asm volatile("cp.async.commit_group;\n");
    };

    prefetch(0, 0);

    int s = 0;
    for (int k0 = 0; k0 < Klen; k0 += BKK, s ^= 1) {
        const bool has_next = (k0 + BKK) < Klen;
        if (has_next) prefetch(s ^ 1, k0 + BKK);
        if (has_next) asm volatile("cp.async.wait_group 1;\n");
        else          asm volatile("cp.async.wait_group 0;\n");
        __syncthreads();

        const float* As = Asf + s * STG_A;
        const float* Bs = Bsf + s * STG_B;
        #pragma unroll
        for (int kk = 0; kk < BKK; kk += 8) {
            uint32_t af[4][4], bf[4][2];
            #pragma unroll
            for (int mt = 0; mt < 4; ++mt) {
                const int r = wm + mt * 16 + gid;
                af[mt][0] = tf32b(As[ r      * SROW + kk + tig    ]);
                af[mt][1] = tf32b(As[(r + 8) * SROW + kk + tig    ]);
                af[mt][2] = tf32b(As[ r      * SROW + kk + tig + 4]);
                af[mt][3] = tf32b(As[(r + 8) * SROW + kk + tig + 4]);
            }
            #pragma unroll
            for (int nt = 0; nt < 4; ++nt) {
                const int r = wn + nt * 8 + gid;
                bf[nt][0] = tf32b(Bs[r * SROW + kk + tig    ]);
                bf[nt][1] = tf32b(Bs[r * SROW + kk + tig + 4]);
            }
            #pragma unroll
            for (int mt = 0; mt < 4; ++mt)
                #pragma unroll
                for (int nt = 0; nt < 4; ++nt)
                    mma_tf32(acc[mt][nt], af[mt], bf[nt]);
        }
        __syncthreads();
    }

    #pragma unroll
    for (int mt = 0; mt < 4; ++mt) {
        const int ma = m0 + wm + mt * 16 + gid;
        const int mb = ma + 8;
        #pragma unroll
        for (int nt = 0; nt < 4; ++nt) {
            const int col = n0 + wn + nt * 8 + 2 * tig;
            if (ma < M) {
                const long long r = crow ? crow[ma] : ma;
                *(float2*)(C + r * (long long)ldc + col) = make_float2(acc[mt][nt][0], acc[mt][nt][1]);
            }
            if (mb < M) {
                const long long r = crow ? crow[mb] : mb;
                *(float2*)(C + r * (long long)ldc + col) = make_float2(acc[mt][nt][2], acc[mt][nt][3]);
            }
        }
    }
}

// ---- stage 2 fused grid: routed down (16x6x32) + shared down (16x8) ----
#define R2_BLOCKS (16 * 6 * EE)              // 3072
#define S2_BLOCKS (16 * 8)                   // 128
__global__ void __launch_bounds__(256, 2) gemm_stage2(const float* __restrict__ w2,
                                                      const float* __restrict__ sdn,
                                                      float* __restrict__ out) {
    const int bid = blockIdx.x;
    if (bid < R2_BLOCKS) {
        const int e   = bid / 96;
        const int rem = bid % 96;
        const int by  = rem / 16, bx = rem % 16;
        const int M = min(g_cnt[e], CAPE);
        gemm_tc_body(bx, by, g_h, IMOE,
                     w2 + (long long)e * HH * IMOE,
                     g_y, HH,
                     g_slot_flat + e*CAPE, g_slot_flat + e*CAPE,
                     M, IMOE);
    } else {
        const int sid = bid - R2_BLOCKS;
        const int by = sid / 16, bx = sid % 16;
        gemm_tc_body(bx, by, g_h_sh, ISH, sdn, out, HH, nullptr, nullptr, TT, ISH);
    }
}

// ---------------- combine: out += SCALE * sum_k w_k * y_k ----------------
__global__ void combine_kernel(float* __restrict__ out) {
    const int t = blockIdx.x;
    const int base = t * TOPK;
    float w[TOPK];
    #pragma unroll
    for (int k = 0; k < TOPK; ++k) w[k] = g_wcomb[base + k];
    float* orow = out + (long long)t * HH;
    for (int h = threadIdx.x; h < HH; h += blockDim.x) {
        float r = 0.f;
        #pragma unroll
        for (int k = 0; k < TOPK; ++k)
            r += w[k] * g_y[(long long)(base + k) * HH + h];
        orow[h] += RSCALE * r;
    }
}

// ---------------- launch ----------------
extern "C" void kernel_launch(void* const* d_in, const int* in_sizes, int n_in,
                              void* d_out, int out_size) {
    const float* x     = (const float*)d_in[0];   // [T,H]
    const float* gatew = (const float*)d_in[1];   // [E,H]
    const float* w13   = (const float*)d_in[2];   // [E,2I,H]
    const float* w2    = (const float*)d_in[3];   // [E,H,I]
    const float* sgu   = (const float*)d_in[4];   // [2*ISH,H]
    const float* sdn   = (const float*)d_in[5];   // [H,ISH]
    float* out = (float*)d_out;                   // [T,H]

    static bool attr_set = false;
    if (!attr_set) {
        cudaFuncSetAttribute(gemm_stage1, cudaFuncAttributeMaxDynamicSharedMemorySize, S1_SMEM);
        cudaFuncSetAttribute(gemm_stage2, cudaFuncAttributeMaxDynamicSharedMemorySize, S2_SMEM);
        attr_set = true;
    }

    init_kernel<<<1, 32>>>();
    logits_kernel<<<TT/4, 128>>>(x, gatew);
    select_kernel<<<4, 256>>>();

    // stage 1: fused gate+up GEMM + SiLU epilogue (routed + shared in one grid)
    gemm_stage1<<<R1_BLOCKS + S1_BLOCKS, 256, S1_SMEM>>>(x, w13, sgu);

    // stage 2: routed down + shared down in one grid (shared writes out fully)
    gemm_stage2<<<R2_BLOCKS + S2_BLOCKS, 256, S2_SMEM>>>(w2, sdn, out);

    // combine routed into out
    combine_kernel<<<TT, 256>>>(out);
}

// round 17
// speedup vs baseline: 1.0736x; 1.0104x over previous
#include <cuda_runtime.h>
#include <cuda_bf16.h>
#include <math.h>
#include <stdint.h>

// ---------------- problem constants ----------------
#define TT     1024      // tokens
#define HH     2048      // hidden
#define EE     32        // routed experts
#define TOPK   6
#define NGROUP 8
#define TOPKG  3
#define EPG    (EE/NGROUP)   // 4 experts per group
#define IMOE   768
#define ISH    1536          // 2 * IMOE
#define CAPE   768           // per-expert capacity
#define RSCALE 16.0f

// ---------------- scratch (static device globals; no allocation) ----------------
__device__ float g_logits[(size_t)TT*EE];            // router logits [1024,32]
__device__ float g_h    [(size_t)TT*TOPK * IMOE];    // routed silu*up          [6144, 768]
__device__ float g_h_sh [(size_t)TT * ISH];          // shared silu*up          [1024,1536]
__device__ float g_wcomb[TT*TOPK];                   // combine weights (0 if dropped)
__device__ int   g_slot_tok [EE*CAPE];               // token index per expert slot
__device__ int   g_slot_flat[EE*CAPE];               // flat (t*K+k) per expert slot
__device__ int   g_cnt[EE];                          // per-expert assignment count

// ---------------- router logits: one thread per (t,e), SEQUENTIAL ascending-k fp32 fma ----
// Bit-replicates the reference's per-output single-accumulator ascending-k chain.
// DO NOT TOUCH: this exact ordering is what makes routing decisions match.
// (block 0 also zeroes the per-expert counters used by select_kernel, which runs after)
__global__ void logits_kernel(const float* __restrict__ x,
                              const float* __restrict__ gate_w) {
    __shared__ float sx[4][HH];               // 4 tokens staged, 32KB
    if (blockIdx.x == 0 && threadIdx.x < EE) g_cnt[threadIdx.x] = 0;
    const int t0 = blockIdx.x * 4;
    const int tid = threadIdx.x;              // 128 threads: 4 tokens x 32 experts
    for (int i = tid; i < 4*HH; i += 128)
        sx[i >> 11][i & (HH-1)] = x[(size_t)(t0 + (i >> 11)) * HH + (i & (HH-1))];
    __syncthreads();

    const int tl = tid & 3;
    const int e  = tid >> 2;
    const float* gw = gate_w + (size_t)e * HH;
    float acc = 0.f;
    #pragma unroll 8
    for (int k = 0; k < HH; ++k)
        acc = fmaf(sx[tl][k], gw[k], acc);    // single chain, ascending k
    g_logits[(size_t)(t0 + tl) * EE + e] = acc;
}

// ---------------- selection: fp32 softmax (jax form) + group-limited top-k + dispatch ----
__global__ void select_kernel() {
    const int t = blockIdx.x * blockDim.x + threadIdx.x;
    if (t >= TT) return;
    const float* l = g_logits + (size_t)t * EE;

    float mx = l[0];
    for (int e = 1; e < EE; ++e) mx = fmaxf(mx, l[e]);
    float ex[EE]; float sum = 0.f;
    for (int e = 0; e < EE; ++e) { ex[e] = expf(l[e] - mx); sum += ex[e]; }
    float sc[EE];
    for (int e = 0; e < EE; ++e) sc[e] = ex[e] / sum;

    float gs[NGROUP];
    for (int g = 0; g < NGROUP; ++g) {
        float m = sc[g * EPG];
        for (int j = 1; j < EPG; ++j) m = fmaxf(m, sc[g * EPG + j]);
        gs[g] = m;
    }
    bool gsel[NGROUP];
    for (int g = 0; g < NGROUP; ++g) gsel[g] = false;
    for (int r = 0; r < TOPKG; ++r) {
        int best = -1; float bv = -1e30f;
        for (int g = 0; g < NGROUP; ++g)
            if (!gsel[g] && gs[g] > bv) { bv = gs[g]; best = g; }
        gsel[best] = true;
    }
    float ms[EE];
    for (int e = 0; e < EE; ++e) ms[e] = gsel[e / EPG] ? sc[e] : 0.f;
    for (int k = 0; k < TOPK; ++k) {
        int best = 0; float bv = -1.f;
        for (int e = 0; e < EE; ++e)
            if (ms[e] > bv) { bv = ms[e]; best = e; }
        ms[best] = -1.f;
        const int flat = t * TOPK + k;
        const int pos = atomicAdd(&g_cnt[best], 1);
        if (pos < CAPE) {
            g_slot_tok [best * CAPE + pos] = t;
            g_slot_flat[best * CAPE + pos] = flat;
            g_wcomb[flat] = bv;
        } else {
            g_wcomb[flat] = 0.f;
        }
    }
}

// ---------------- shared GEMM machinery (R8 numerics) ----------------
#define BKK 32
#define SPAD 4
#define SROW (BKK + SPAD)           // 36 words; 144B row stride (16B-aligned)

__device__ __forceinline__ uint32_t tf32b(float x) {
    uint32_t u;
    asm("cvt.rna.tf32.f32 %0, %1;" : "=r"(u) : "f"(x));
    return u;
}

__device__ __forceinline__ void mma_tf32(float c[4], const uint32_t a[4], const uint32_t b[2]) {
    asm volatile(
        "mma.sync.aligned.m16n8k8.row.col.f32.tf32.tf32.f32 "
        "{%0,%1,%2,%3}, {%4,%5,%6,%7}, {%8,%9}, {%0,%1,%2,%3};\n"
        : "+f"(c[0]), "+f"(c[1]), "+f"(c[2]), "+f"(c[3])
        : "r"(a[0]), "r"(a[1]), "r"(a[2]), "r"(a[3]), "r"(b[0]), "r"(b[1]));
}

__device__ __forceinline__ void cp16(uint32_t smem_addr, const float* gptr, int srcsize) {
    asm volatile("cp.async.cg.shared.global [%0], [%1], 16, %2;\n"
                 :: "r"(smem_addr), "l"(gptr), "r"(srcsize));
}

// ================= STAGE 1: fused gate+up GEMM with SiLU epilogue =================
// Block computes a [128 rows x 64 inter-cols] slice of BOTH gate and up halves,
// then writes h = silu(g)*u directly. Same mma/slab count as the 128x128 body.
#define S1_STG_A  (128 * SROW)               // 4608 floats
#define S1_STG_B  (64 * SROW)                // 2304 floats
#define S1_SMEM   ((2*S1_STG_A + 4*S1_STG_B) * 4)   // 73728 B

__device__ __forceinline__ void gemm_swiglu_body(
    int bx, int by,
    const float* __restrict__ A, int lda,
    const float* __restrict__ B, int uoff,   // gate rows at B, up rows at B+uoff rows
    float* __restrict__ Hout, int ldh,
    const int* __restrict__ arow,            // nullable
    const int* __restrict__ crow,            // nullable
    int M, int Klen)
{
    const int m0 = by * 128;
    if (m0 >= M) return;
    const int n0h = bx * 64;                  // intermediate-col slice base

    extern __shared__ float smem[];
    float* Asf = smem;                        // [2][128][SROW]
    float* Bgf = smem + 2 * S1_STG_A;         // [2][64][SROW]
    float* Buf = Bgf + 2 * S1_STG_B;          // [2][64][SROW]
    const uint32_t sb = (uint32_t)__cvta_generic_to_shared(smem);
    const uint32_t As_u = sb;
    const uint32_t Bg_u = sb + 2 * S1_STG_A * 4;
    const uint32_t Bu_u = Bg_u + 2 * S1_STG_B * 4;

    const int tid  = threadIdx.x;
    const int warp = tid >> 5, lane = tid & 31;
    const int wm = (warp & 3) * 32;           // 4 warps along m
    const int wn = (warp >> 2) * 32;          // 2 warps along n (64 cols)
    const int gid = lane >> 2, tig = lane & 3;

    const int lrow = tid >> 3;                // 0..31
    const int lcol = (tid & 7) * 4;

    long long arows[4]; int asz[4];
    #pragma unroll
    for (int p = 0; p < 4; ++p) {
        const int m = m0 + lrow + p * 32;
        const bool ok = m < M;
        asz[p] = ok ? 16 : 0;
        arows[p] = ok ? (arow ? arow[m] : m) : 0;
    }
    const long long bgrow = (long long)(n0h + lrow) * Klen;
    const long long burow = (long long)(uoff + n0h + lrow) * Klen;

    float accG[2][4][4], accU[2][4][4];
    #pragma unroll
    for (int i = 0; i < 2; ++i)
        #pragma unroll
        for (int j = 0; j < 4; ++j)
            #pragma unroll
            for (int r = 0; r < 4; ++r) { accG[i][j][r] = 0.f; accU[i][j][r] = 0.f; }

    auto prefetch = [&](int st, int k0) {
        const uint32_t ab = As_u + (uint32_t)(st * S1_STG_A) * 4;
        const uint32_t gb = Bg_u + (uint32_t)(st * S1_STG_B) * 4;
        const uint32_t ub = Bu_u + (uint32_t)(st * S1_STG_B) * 4;
        #pragma unroll
        for (int p = 0; p < 4; ++p)
            cp16(ab + (uint32_t)((lrow + p * 32) * SROW + lcol) * 4,
                 A + arows[p] * (long long)lda + k0 + lcol, asz[p]);
        #pragma unroll
        for (int p = 0; p < 2; ++p) {
            cp16(gb + (uint32_t)((lrow + p * 32) * SROW + lcol) * 4,
                 B + bgrow + (long long)p * 32 * Klen + k0 + lcol, 16);
            cp16(ub + (uint32_t)((lrow + p * 32) * SROW + lcol) * 4,
                 B + burow + (long long)p * 32 * Klen + k0 + lcol, 16);
        }
        asm volatile("cp.async.commit_group;\n");
    };

    prefetch(0, 0);

    int s = 0;
    for (int k0 = 0; k0 < Klen; k0 += BKK, s ^= 1) {
        const bool has_next = (k0 + BKK) < Klen;
        if (has_next) prefetch(s ^ 1, k0 + BKK);
        if (has_next) asm volatile("cp.async.wait_group 1;\n");
        else          asm volatile("cp.async.wait_group 0;\n");
        __syncthreads();

        const float* As = Asf + s * S1_STG_A;
        const float* Bg = Bgf + s * S1_STG_B;
        const float* Bu = Buf + s * S1_STG_B;
        #pragma unroll
        for (int kk = 0; kk < BKK; kk += 8) {
            uint32_t af[2][4], bg[4][2], bu[4][2];
            #pragma unroll
            for (int mt = 0; mt < 2; ++mt) {
                const int r = wm + mt * 16 + gid;
                af[mt][0] = tf32b(As[ r      * SROW + kk + tig    ]);
                af[mt][1] = tf32b(As[(r + 8) * SROW + kk + tig    ]);
                af[mt][2] = tf32b(As[ r      * SROW + kk + tig + 4]);
                af[mt][3] = tf32b(As[(r + 8) * SROW + kk + tig + 4]);
            }
            #pragma unroll
            for (int nt = 0; nt < 4; ++nt) {
                const int r = wn + nt * 8 + gid;
                bg[nt][0] = tf32b(Bg[r * SROW + kk + tig    ]);
                bg[nt][1] = tf32b(Bg[r * SROW + kk + tig + 4]);
                bu[nt][0] = tf32b(Bu[r * SROW + kk + tig    ]);
                bu[nt][1] = tf32b(Bu[r * SROW + kk + tig + 4]);
            }
            #pragma unroll
            for (int mt = 0; mt < 2; ++mt)
                #pragma unroll
                for (int nt = 0; nt < 4; ++nt) {
                    mma_tf32(accG[mt][nt], af[mt], bg[nt]);
                    mma_tf32(accU[mt][nt], af[mt], bu[nt]);
                }
        }
        __syncthreads();
    }

    // fused SiLU epilogue: h = u * g / (1 + exp(-g)); same formula as before
    #pragma unroll
    for (int mt = 0; mt < 2; ++mt) {
        const int ma = m0 + wm + mt * 16 + gid;
        const int mb = ma + 8;
        #pragma unroll
        for (int nt = 0; nt < 4; ++nt) {
            const int col = n0h + wn + nt * 8 + 2 * tig;
            if (ma < M) {
                const float g0 = accG[mt][nt][0], u0 = accU[mt][nt][0];
                const float g1 = accG[mt][nt][1], u1 = accU[mt][nt][1];
                const long long r = crow ? crow[ma] : ma;
                *(float2*)(Hout + r * (long long)ldh + col) =
                    make_float2(u0 * g0 / (1.f + expf(-g0)), u1 * g1 / (1.f + expf(-g1)));
            }
            if (mb < M) {
                const float g2 = accG[mt][nt][2], u2 = accU[mt][nt][2];
                const float g3 = accG[mt][nt][3], u3 = accU[mt][nt][3];
                const long long r = crow ? crow[mb] : mb;
                *(float2*)(Hout + r * (long long)ldh + col) =
                    make_float2(u2 * g2 / (1.f + expf(-g2)), u3 * g3 / (1.f + expf(-g3)));
            }
        }
    }
}

// ---- stage 1 fused grid: routed (12 slices x 6 y x 32 e) + shared (24 slices x 8 y) ----
#define R1_BLOCKS (12 * 6 * EE)              // 2304
#define S1_BLOCKS (24 * 8)                   // 192
__global__ void __launch_bounds__(256, 2) gemm_stage1(const float* __restrict__ x,
                                                      const float* __restrict__ w13,
                                                      const float* __restrict__ sgu) {
    const int bid = blockIdx.x;
    if (bid < R1_BLOCKS) {
        const int e   = bid / 72;
        const int rem = bid % 72;
        const int by  = rem / 12, bx = rem % 12;
        const int M = min(g_cnt[e], CAPE);
        gemm_swiglu_body(bx, by, x, HH,
                         w13 + (long long)e * (2*IMOE) * HH, IMOE,
                         g_h, IMOE,
                         g_slot_tok + e*CAPE, g_slot_flat + e*CAPE,
                         M, HH);
    } else {
        const int sid = bid - R1_BLOCKS;
        const int by = sid / 24, bx = sid % 24;
        gemm_swiglu_body(bx, by, x, HH, sgu, ISH, g_h_sh, ISH,
                         nullptr, nullptr, TT, HH);
    }
}

// ================= STAGE 2: 128x128 GEMM with fused combine epilogue =================
// Routed blocks: out[flat/TOPK] += RSCALE * wcomb[flat] * acc  (atomic)
// Shared blocks: out[m] += acc  (atomic; out zero-initialized by memset)
#define BM 128
#define BN 128
#define STG_A (BM * SROW)
#define STG_B (BN * SROW)
#define S2_SMEM ((2*STG_A + 2*STG_B) * 4)    // 73728 B

__device__ __forceinline__ void gemm_combine_body(
    int bx, int by,
    const float* __restrict__ A, int lda,
    const float* __restrict__ B,
    float* __restrict__ out,                 // [TT, HH], zero-initialized
    const int* __restrict__ arow,            // nullable (routed: g_slot_flat)
    const int* __restrict__ crow,            // nullable (routed: g_slot_flat)
    int M, int Klen, bool routed)
{
    const int m0 = by * BM;
    if (m0 >= M) return;
    const int n0 = bx * BN;

    extern __shared__ float smem[];
    float* Asf = smem;
    float* Bsf = smem + 2 * STG_A;
    const uint32_t smem_base = (uint32_t)__cvta_generic_to_shared(smem);
    const uint32_t As_u = smem_base;
    const uint32_t Bs_u = smem_base + 2 * STG_A * 4;

    const int tid  = threadIdx.x;
    const int warp = tid >> 5, lane = tid & 31;
    const int wm = (warp & 1) * 64;
    const int wn = (warp >> 1) * 32;
    const int gid = lane >> 2, tig = lane & 3;

    const int lrow = tid >> 3;
    const int lcol = (tid & 7) * 4;

    long long arows[4]; int asz[4];
    #pragma unroll
    for (int p = 0; p < 4; ++p) {
        const int m = m0 + lrow + p * 32;
        const bool ok = m < M;
        asz[p] = ok ? 16 : 0;
        arows[p] = ok ? (arow ? arow[m] : m) : 0;
    }
    const long long brow = (long long)(n0 + lrow) * Klen;

    float acc[4][4][4];
    #pragma unroll
    for (int i = 0; i < 4; ++i)
        #pragma unroll
        for (int j = 0; j < 4; ++j)
            #pragma unroll
            for (int r = 0; r < 4; ++r) acc[i][j][r] = 0.f;

    auto prefetch = [&](int st, int k0) {
        const uint32_t abase = As_u + (uint32_t)(st * STG_A) * 4;
        const uint32_t bbase = Bs_u + (uint32_t)(st * STG_B) * 4;
        #pragma unroll
        for (int p = 0; p < 4; ++p) {
            const int r = lrow + p * 32;
            cp16(abase + (uint32_t)(r * SROW + lcol) * 4,
                 A + arows[p] * (long long)lda + k0 + lcol, asz[p]);
            cp16(bbase + (uint32_t)(r * SROW + lcol) * 4,
                 B + brow + (long long)p * 32 * Klen + k0 + lcol, 16);
        }
        asm volatile("cp.async.commit_group;\n");
    };

    prefetch(0, 0);

    int s = 0;
    for (int k0 = 0; k0 < Klen; k0 += BKK, s ^= 1) {
        const bool has_next = (k0 + BKK) < Klen;
        if (has_next) prefetch(s ^ 1, k0 + BKK);
        if (has_next) asm volatile("cp.async.wait_group 1;\n");
        else          asm volatile("cp.async.wait_group 0;\n");
        __syncthreads();

        const float* As = Asf + s * STG_A;
        const float* Bs = Bsf + s * STG_B;
        #pragma unroll
        for (int kk = 0; kk < BKK; kk += 8) {
            uint32_t af[4][4], bf[4][2];
            #pragma unroll
            for (int mt = 0; mt < 4; ++mt) {
                const int r = wm + mt * 16 + gid;
                af[mt][0] = tf32b(As[ r      * SROW + kk + tig    ]);
                af[mt][1] = tf32b(As[(r + 8) * SROW + kk + tig    ]);
                af[mt][2] = tf32b(As[ r      * SROW + kk + tig + 4]);
                af[mt][3] = tf32b(As[(r + 8) * SROW + kk + tig + 4]);
            }
            #pragma unroll
            for (int nt = 0; nt < 4; ++nt) {
                const int r = wn + nt * 8 + gid;
                bf[nt][0] = tf32b(Bs[r * SROW + kk + tig    ]);
                bf[nt][1] = tf32b(Bs[r * SROW + kk + tig + 4]);
            }
            #pragma unroll
            for (int mt = 0; mt < 4; ++mt)
                #pragma unroll
                for (int nt = 0; nt < 4; ++nt)
                    mma_tf32(acc[mt][nt], af[mt], bf[nt]);
        }
        __syncthreads();
    }

    // fused combine epilogue: atomic adds into out
    #pragma unroll
    for (int half = 0; half < 2; ++half) {
        #pragma unroll
        for (int mt = 0; mt < 4; ++mt) {
            const int m = m0 + wm + mt * 16 + gid + half * 8;
            if (m >= M) continue;
            long long orow_idx; float scale;
            if (routed) {
                const int flat = crow[m];
                orow_idx = flat / TOPK;
                scale = RSCALE * g_wcomb[flat];
            } else {
                orow_idx = m;
                scale = 1.f;
            }
            float* orow = out + orow_idx * (long long)HH;
            #pragma unroll
            for (int nt = 0; nt < 4; ++nt) {
                const int col = n0 + wn + nt * 8 + 2 * tig;
                atomicAdd(orow + col,     scale * acc[mt][nt][half * 2]);
                atomicAdd(orow + col + 1, scale * acc[mt][nt][half * 2 + 1]);
            }
        }
    }
}

// ---- stage 2 fused grid: routed down (16x6x32) + shared down (16x8) ----
#define R2_BLOCKS (16 * 6 * EE)              // 3072
#define S2_BLOCKS (16 * 8)                   // 128
__global__ void __launch_bounds__(256, 2) gemm_stage2(const float* __restrict__ w2,
                                                      const float* __restrict__ sdn,
                                                      float* __restrict__ out) {
    const int bid = blockIdx.x;
    if (bid < R2_BLOCKS) {
        const int e   = bid / 96;
        const int rem = bid % 96;
        const int by  = rem / 16, bx = rem % 16;
        const int M = min(g_cnt[e], CAPE);
        gemm_combine_body(bx, by, g_h, IMOE,
                          w2 + (long long)e * HH * IMOE,
                          out,
                          g_slot_flat + e*CAPE, g_slot_flat + e*CAPE,
                          M, IMOE, true);
    } else {
        const int sid = bid - R2_BLOCKS;
        const int by = sid / 16, bx = sid % 16;
        gemm_combine_body(bx, by, g_h_sh, ISH, sdn, out,
                          nullptr, nullptr, TT, ISH, false);
    }
}

// ---------------- launch ----------------
extern "C" void kernel_launch(void* const* d_in, const int* in_sizes, int n_in,
                              void* d_out, int out_size) {
    const float* x     = (const float*)d_in[0];   // [T,H]
    const float* gatew = (const float*)d_in[1];   // [E,H]
    const float* w13   = (const float*)d_in[2];   // [E,2I,H]
    const float* w2    = (const float*)d_in[3];   // [E,H,I]
    const float* sgu   = (const float*)d_in[4];   // [2*ISH,H]
    const float* sdn   = (const float*)d_in[5];   // [H,ISH]
    float* out = (float*)d_out;                   // [T,H]

    static bool attr_set = false;
    if (!attr_set) {
        cudaFuncSetAttribute(gemm_stage1, cudaFuncAttributeMaxDynamicSharedMemorySize, S1_SMEM);
        cudaFuncSetAttribute(gemm_stage2, cudaFuncAttributeMaxDynamicSharedMemorySize, S2_SMEM);
        attr_set = true;
    }

    // router (logits_kernel also zeroes g_cnt in block 0)
    logits_kernel<<<TT/4, 128>>>(x, gatew);
    select_kernel<<<4, 256>>>();

    // zero the output accumulator (graph-capturable async memset)
    cudaMemsetAsync(out, 0, (size_t)out_size * sizeof(float), 0);

    // stage 1: fused gate+up GEMM + SiLU epilogue (routed + shared in one grid)
    gemm_stage1<<<R1_BLOCKS + S1_BLOCKS, 256, S1_SMEM>>>(x, w13, sgu);

    // stage 2: down GEMMs with fused combine epilogue (atomic adds into out)
    gemm_stage2<<<R2_BLOCKS + S2_BLOCKS, 256, S2_SMEM>>>(w2, sdn, out);
}